// round 15
// baseline (speedup 1.0000x reference)
#include <cuda_runtime.h>

// ConvCapsuleLayer: B=2, H=W=48, IN_CAPS=8, ATOMS=16, KER=3, OUT_CAPS=16, ROUTINGS=3
// Ho=Wo=46, N = 4232 positions. One CTA (128 threads) per position.
//
// Thread = (i = tid>>4, o = tid&15); lane = (i&1)*16 + o. Routing logits in
// registers; softmax-over-o via shfl_xor butterfly (no max subtraction: the
// logits are bounded ~10 here). W[i,o] register-resident (scalar float4).
// F (logit update) + A (softmax) + B (P-accumulation) fused into ONE pass over
// the 36 pose rows per iteration (R12's winning change).
//
// R15 delta: __launch_bounds__(128,6) — cap 85 regs. Live-set audit of the
// fused loop: W(16)+l(9)+P(16)+Q(16)+pose(16)+scalars(~10) ~= 83 regs, so the
// true demand fits under the 6-CTA boundary (65536/768 = 85); the 96 ptxas
// chose under the 5-CTA cap was slack, not need. (R7 lesson: only force
// occupancy when the squeeze is small; this is 12 regs into a fitting budget.)

#define HH 48
#define WW 48
#define CIN 136
#define HO 46
#define WO 46
#define NTH 128
#define ROUTINGS 3
#define VSTR 20   // v_s row stride: float4-aligned rows

#define DOT4(p, q) ((p).x*(q).x + (p).y*(q).y + (p).z*(q).z + (p).w*(q).w)

__global__ __launch_bounds__(NTH, 6)
void capsule_kernel(const float* __restrict__ x,
                    const float* __restrict__ Wg,
                    float* __restrict__ out)
{
    __shared__ __align__(16) float pose_s[72 * 16];   // [ki][a*4+b]
    __shared__ float act_s[72];
    __shared__ __align__(16) float spart[4][16 * 20]; // [warp][o*20 + e], padded
    __shared__ __align__(16) float v_s[16 * VSTR];    // [o][e], stride 20

    const int tid = threadIdx.x;
    const int n   = blockIdx.x;
    const int b   = n / (HO * WO);
    const int rem = n % (HO * WO);
    const int ho  = rem / WO;
    const int wo  = rem % WO;

    const int i_  = tid >> 4;   // 0..7
    const int o_  = tid & 15;   // 0..15
    const int wrp = tid >> 5;   // 0..3

    // ---- W[i_,o_] into registers (warp reads 2KB contiguous) ----
    const float4* wg = (const float4*)&Wg[tid * 16];
    const float4 w0 = wg[0], w1 = wg[1], w2 = wg[2], w3 = wg[3];

    // ---- load pose + act ----
    for (int idx = tid; idx < 72 * 17; idx += NTH) {
        int ki = idx / 17;
        int a  = idx - ki * 17;
        int k  = ki >> 3;
        int i  = ki & 7;
        int di = k / 3;
        int dj = k - di * 3;
        float val = x[(size_t)(((b * HH + ho + di) * WW) + (wo + dj)) * CIN + i * 17 + a];
        if (a < 16) pose_s[ki * 16 + a] = val;
        else        act_s[ki] = val;
    }
    __syncthreads();

    // ---- routing logits in registers: l[k] = logits[k*8+i_][o_] ----
    float l[9];
    #pragma unroll
    for (int k = 0; k < 9; k++) l[k] = 0.0f;

    float4 P0, P1, P2, P3;   // P[i_,o_] rows (accumulated per iteration)

    // ================= iteration r = 0 prologue: coup = act/16 =================
    {
        P0 = make_float4(0.f,0.f,0.f,0.f);
        P1 = make_float4(0.f,0.f,0.f,0.f);
        P2 = make_float4(0.f,0.f,0.f,0.f);
        P3 = make_float4(0.f,0.f,0.f,0.f);
        #pragma unroll
        for (int k = 0; k < 9; k++) {
            const float c = act_s[k * 8 + i_] * 0.0625f;
            const float4* pr = (const float4*)&pose_s[(k * 8 + i_) * 16];  // bcast
            float4 p0 = pr[0], p1 = pr[1], p2 = pr[2], p3 = pr[3];
            P0.x += c*p0.x; P0.y += c*p0.y; P0.z += c*p0.z; P0.w += c*p0.w;
            P1.x += c*p1.x; P1.y += c*p1.y; P1.z += c*p1.z; P1.w += c*p1.w;
            P2.x += c*p2.x; P2.y += c*p2.y; P2.z += c*p2.z; P2.w += c*p2.w;
            P3.x += c*p3.x; P3.y += c*p3.y; P3.z += c*p3.z; P3.w += c*p3.w;
        }
    }

    #pragma unroll
    for (int r = 0; r < ROUTINGS; r++) {
        if (r > 0) {
            // ---- E: Q rows from v (smem, float4 rows) and W (regs) ----
            float4 Q0, Q1, Q2, Q3;
            {
                const float4* vr = (const float4*)&v_s[o_ * VSTR];
                #pragma unroll
                for (int a = 0; a < 4; a++) {
                    float4 va = vr[a];
                    float4 Qa;
                    Qa.x = DOT4(va, w0);
                    Qa.y = DOT4(va, w1);
                    Qa.z = DOT4(va, w2);
                    Qa.w = DOT4(va, w3);
                    if (a == 0) Q0 = Qa; else if (a == 1) Q1 = Qa;
                    else if (a == 2) Q2 = Qa; else Q3 = Qa;
                }
            }
            // ---- F+A+B fused: one pass over pose rows per k ----
            P0 = make_float4(0.f,0.f,0.f,0.f);
            P1 = make_float4(0.f,0.f,0.f,0.f);
            P2 = make_float4(0.f,0.f,0.f,0.f);
            P3 = make_float4(0.f,0.f,0.f,0.f);
            #pragma unroll
            for (int k = 0; k < 9; k++) {
                const float4* pr = (const float4*)&pose_s[(k * 8 + i_) * 16]; // bcast
                float4 p0 = pr[0], p1 = pr[1], p2 = pr[2], p3 = pr[3];
                // F: logit update with v from previous iteration
                l[k] += DOT4(p0, Q0) + DOT4(p1, Q1) + DOT4(p2, Q2) + DOT4(p3, Q3);
                // A: softmax over o (no max subtraction; |l| bounded ~10)
                float e = __expf(l[k]);
                float s = e;
                s += __shfl_xor_sync(0xffffffffu, s, 1);
                s += __shfl_xor_sync(0xffffffffu, s, 2);
                s += __shfl_xor_sync(0xffffffffu, s, 4);
                s += __shfl_xor_sync(0xffffffffu, s, 8);
                const float c = e * __fdividef(act_s[k * 8 + i_], s);
                // B: P-accumulate, reusing the loaded pose rows
                P0.x += c*p0.x; P0.y += c*p0.y; P0.z += c*p0.z; P0.w += c*p0.w;
                P1.x += c*p1.x; P1.y += c*p1.y; P1.z += c*p1.z; P1.w += c*p1.w;
                P2.x += c*p2.x; P2.y += c*p2.y; P2.z += c*p2.z; P2.w += c*p2.w;
                P3.x += c*p3.x; P3.y += c*p3.y; P3.z += c*p3.z; P3.w += c*p3.w;
            }
        }

        // ---- C: M = P @ W (regs); shfl(16) i-pair reduce; split-store spart ----
        {
            float4 M[4];
            #pragma unroll
            for (int a = 0; a < 4; a++) {
                float4 Pa = (a == 0) ? P0 : (a == 1) ? P1 : (a == 2) ? P2 : P3;
                float4 Ma;
                Ma.x = Pa.x*w0.x + Pa.y*w1.x + Pa.z*w2.x + Pa.w*w3.x;
                Ma.y = Pa.x*w0.y + Pa.y*w1.y + Pa.z*w2.y + Pa.w*w3.y;
                Ma.z = Pa.x*w0.z + Pa.y*w1.z + Pa.z*w2.z + Pa.w*w3.z;
                Ma.w = Pa.x*w0.w + Pa.y*w1.w + Pa.z*w2.w + Pa.w*w3.w;
                Ma.x += __shfl_xor_sync(0xffffffffu, Ma.x, 16);
                Ma.y += __shfl_xor_sync(0xffffffffu, Ma.y, 16);
                Ma.z += __shfl_xor_sync(0xffffffffu, Ma.z, 16);
                Ma.w += __shfl_xor_sync(0xffffffffu, Ma.w, 16);
                M[a] = Ma;
            }
            float4* dst = (float4*)&spart[wrp][o_ * 20];
            if ((tid & 16) == 0) { dst[0] = M[0]; dst[1] = M[1]; }
            else                 { dst[2] = M[2]; dst[3] = M[3]; }
        }
        __syncthreads();

        // ---- D: s = sum_w spart; squash via shfl; write v (stride-20) or out ----
        {
            const int o = tid >> 3, g = tid & 7;
            const int off = o * 20 + g * 2;
            float2 a0 = *(const float2*)&spart[0][off];
            float2 a1 = *(const float2*)&spart[1][off];
            float2 a2 = *(const float2*)&spart[2][off];
            float2 a3 = *(const float2*)&spart[3][off];
            float2 sv = make_float2(a0.x + a1.x + a2.x + a3.x,
                                    a0.y + a1.y + a2.y + a3.y);
            float part = sv.x * sv.x + sv.y * sv.y;
            part += __shfl_xor_sync(0xffffffffu, part, 1);
            part += __shfl_xor_sync(0xffffffffu, part, 2);
            part += __shfl_xor_sync(0xffffffffu, part, 4);
            const float sq = part;
            const float scale = (sq / (1.0f + sq)) * rsqrtf(sq + 1e-7f);
            float2 vv = make_float2(sv.x * scale, sv.y * scale);
            if (r == ROUTINGS - 1) {
                *(float2*)&out[(size_t)n * 256 + tid * 2] = vv;
            } else {
                *(float2*)&v_s[o * VSTR + g * 2] = vv;
            }
        }
        if (r == ROUTINGS - 1) break;
        __syncthreads();
        // No third barrier: the fused F+A+B touches only registers and
        // read-only pose_s/act_s; its v_s reads (in E) happen right after this
        // barrier, and the next v_s write (next D) is behind the post-C barrier.
    }
}

extern "C" void kernel_launch(void* const* d_in, const int* in_sizes, int n_in,
                              void* d_out, int out_size)
{
    const float* x = (const float*)d_in[0];
    const float* W = (const float*)d_in[1];
    if (n_in >= 2 && in_sizes[0] == 2048) {   // defensive: W has 2048 elems
        const float* t = x; x = W; W = t;
    }
    float* out = (float*)d_out;
    capsule_kernel<<<2 * HO * WO, NTH>>>(x, W, out);
}

// round 17
// speedup vs baseline: 1.5168x; 1.5168x over previous
#include <cuda_runtime.h>

// ConvCapsuleLayer: B=2, H=W=48, IN_CAPS=8, ATOMS=16, KER=3, OUT_CAPS=16, ROUTINGS=3
// Ho=Wo=46, N = 4232 positions. One CTA (128 threads) per position.
//
// Thread = (i = tid>>4, o = tid&15); lane = (i&1)*16 + o. Routing logits in
// registers; softmax-over-o via shfl_xor butterfly (no max subtraction: the
// logits are bounded ~10 here). W[i,o] register-resident (scalar float4).
// F (logit update) + A (softmax) + B (P-accumulation) fused into ONE pass over
// the 36 pose rows per iteration.
//
// Config notes (hard-won): __launch_bounds__(128,5) / ~96 regs is the sweet
// spot. Forcing 6 CTAs (85-reg cap) made ptxas REMATERIALIZE ~60% more dynamic
// instructions (R15: 91us at HIGHER issue%); capping 40 regs below demand
// spills to LMEM (R7: DRAM 46%). Do not force occupancy further.
//
// R16 delta: C-phase shfl_xor(16) i-pair reduction removed. Each thread now
// stores its full M (4x STS.128) into an 8-plane spart (plane = i), and D sums
// 8 partials instead of 4. Removes 16 high-latency SHFLs + predicated stores
// per iteration for +2 STS/+4 LDS. Store pattern (5o+a) mod 8 is a permutation
// -> conflict-free STS.128.

#define HH 48
#define WW 48
#define CIN 136
#define HO 46
#define WO 46
#define NTH 128
#define ROUTINGS 3
#define VSTR 20    // v_s row stride: float4-aligned rows
#define PSTR 320   // spart plane stride: 16 rows * 20 floats

#define DOT4(p, q) ((p).x*(q).x + (p).y*(q).y + (p).z*(q).z + (p).w*(q).w)

__global__ __launch_bounds__(NTH, 5)
void capsule_kernel(const float* __restrict__ x,
                    const float* __restrict__ Wg,
                    float* __restrict__ out)
{
    __shared__ __align__(16) float pose_s[72 * 16];   // [ki][a*4+b]
    __shared__ float act_s[72];
    __shared__ __align__(16) float spart[8 * PSTR];   // [i][o*20 + a*4+c]
    __shared__ __align__(16) float v_s[16 * VSTR];    // [o][e], stride 20

    const int tid = threadIdx.x;
    const int n   = blockIdx.x;
    const int b   = n / (HO * WO);
    const int rem = n % (HO * WO);
    const int ho  = rem / WO;
    const int wo  = rem % WO;

    const int i_  = tid >> 4;   // 0..7
    const int o_  = tid & 15;   // 0..15

    // ---- W[i_,o_] into registers (warp reads 2KB contiguous) ----
    const float4* wg = (const float4*)&Wg[tid * 16];
    const float4 w0 = wg[0], w1 = wg[1], w2 = wg[2], w3 = wg[3];

    // ---- load pose + act ----
    for (int idx = tid; idx < 72 * 17; idx += NTH) {
        int ki = idx / 17;
        int a  = idx - ki * 17;
        int k  = ki >> 3;
        int i  = ki & 7;
        int di = k / 3;
        int dj = k - di * 3;
        float val = x[(size_t)(((b * HH + ho + di) * WW) + (wo + dj)) * CIN + i * 17 + a];
        if (a < 16) pose_s[ki * 16 + a] = val;
        else        act_s[ki] = val;
    }
    __syncthreads();

    // ---- routing logits in registers: l[k] = logits[k*8+i_][o_] ----
    float l[9];
    #pragma unroll
    for (int k = 0; k < 9; k++) l[k] = 0.0f;

    float4 P0, P1, P2, P3;   // P[i_,o_] rows (accumulated per iteration)

    // ================= iteration r = 0 prologue: coup = act/16 =================
    {
        P0 = make_float4(0.f,0.f,0.f,0.f);
        P1 = make_float4(0.f,0.f,0.f,0.f);
        P2 = make_float4(0.f,0.f,0.f,0.f);
        P3 = make_float4(0.f,0.f,0.f,0.f);
        #pragma unroll
        for (int k = 0; k < 9; k++) {
            const float c = act_s[k * 8 + i_] * 0.0625f;
            const float4* pr = (const float4*)&pose_s[(k * 8 + i_) * 16];  // bcast
            float4 p0 = pr[0], p1 = pr[1], p2 = pr[2], p3 = pr[3];
            P0.x += c*p0.x; P0.y += c*p0.y; P0.z += c*p0.z; P0.w += c*p0.w;
            P1.x += c*p1.x; P1.y += c*p1.y; P1.z += c*p1.z; P1.w += c*p1.w;
            P2.x += c*p2.x; P2.y += c*p2.y; P2.z += c*p2.z; P2.w += c*p2.w;
            P3.x += c*p3.x; P3.y += c*p3.y; P3.z += c*p3.z; P3.w += c*p3.w;
        }
    }

    #pragma unroll
    for (int r = 0; r < ROUTINGS; r++) {
        if (r > 0) {
            // ---- E: Q rows from v (smem, float4 rows) and W (regs) ----
            float4 Q0, Q1, Q2, Q3;
            {
                const float4* vr = (const float4*)&v_s[o_ * VSTR];
                #pragma unroll
                for (int a = 0; a < 4; a++) {
                    float4 va = vr[a];
                    float4 Qa;
                    Qa.x = DOT4(va, w0);
                    Qa.y = DOT4(va, w1);
                    Qa.z = DOT4(va, w2);
                    Qa.w = DOT4(va, w3);
                    if (a == 0) Q0 = Qa; else if (a == 1) Q1 = Qa;
                    else if (a == 2) Q2 = Qa; else Q3 = Qa;
                }
            }
            // ---- F+A+B fused: one pass over pose rows per k ----
            P0 = make_float4(0.f,0.f,0.f,0.f);
            P1 = make_float4(0.f,0.f,0.f,0.f);
            P2 = make_float4(0.f,0.f,0.f,0.f);
            P3 = make_float4(0.f,0.f,0.f,0.f);
            #pragma unroll
            for (int k = 0; k < 9; k++) {
                const float4* pr = (const float4*)&pose_s[(k * 8 + i_) * 16]; // bcast
                float4 p0 = pr[0], p1 = pr[1], p2 = pr[2], p3 = pr[3];
                // F: logit update with v from previous iteration
                l[k] += DOT4(p0, Q0) + DOT4(p1, Q1) + DOT4(p2, Q2) + DOT4(p3, Q3);
                // A: softmax over o (no max subtraction; |l| bounded ~10)
                float e = __expf(l[k]);
                float s = e;
                s += __shfl_xor_sync(0xffffffffu, s, 1);
                s += __shfl_xor_sync(0xffffffffu, s, 2);
                s += __shfl_xor_sync(0xffffffffu, s, 4);
                s += __shfl_xor_sync(0xffffffffu, s, 8);
                const float c = e * __fdividef(act_s[k * 8 + i_], s);
                // B: P-accumulate, reusing the loaded pose rows
                P0.x += c*p0.x; P0.y += c*p0.y; P0.z += c*p0.z; P0.w += c*p0.w;
                P1.x += c*p1.x; P1.y += c*p1.y; P1.z += c*p1.z; P1.w += c*p1.w;
                P2.x += c*p2.x; P2.y += c*p2.y; P2.z += c*p2.z; P2.w += c*p2.w;
                P3.x += c*p3.x; P3.y += c*p3.y; P3.z += c*p3.z; P3.w += c*p3.w;
            }
        }

        // ---- C: M = P @ W (regs); store full M to this thread's i-plane ----
        {
            float4* dst = (float4*)&spart[i_ * PSTR + o_ * 20];
            #pragma unroll
            for (int a = 0; a < 4; a++) {
                float4 Pa = (a == 0) ? P0 : (a == 1) ? P1 : (a == 2) ? P2 : P3;
                float4 Ma;
                Ma.x = Pa.x*w0.x + Pa.y*w1.x + Pa.z*w2.x + Pa.w*w3.x;
                Ma.y = Pa.x*w0.y + Pa.y*w1.y + Pa.z*w2.y + Pa.w*w3.y;
                Ma.z = Pa.x*w0.z + Pa.y*w1.z + Pa.z*w2.z + Pa.w*w3.z;
                Ma.w = Pa.x*w0.w + Pa.y*w1.w + Pa.z*w2.w + Pa.w*w3.w;
                dst[a] = Ma;    // (5o+a) mod 8 bank-group pattern: conflict-free
            }
        }
        __syncthreads();

        // ---- D: s[o][e] = sum over 8 i-planes; squash via shfl; v / out ----
        {
            const int o = tid >> 3, g = tid & 7;
            const int off = o * 20 + g * 2;
            float2 sv = make_float2(0.f, 0.f);
            #pragma unroll
            for (int i = 0; i < 8; i++) {
                float2 t = *(const float2*)&spart[i * PSTR + off];
                sv.x += t.x; sv.y += t.y;
            }
            float part = sv.x * sv.x + sv.y * sv.y;
            part += __shfl_xor_sync(0xffffffffu, part, 1);
            part += __shfl_xor_sync(0xffffffffu, part, 2);
            part += __shfl_xor_sync(0xffffffffu, part, 4);
            const float sq = part;
            const float scale = (sq / (1.0f + sq)) * rsqrtf(sq + 1e-7f);
            float2 vv = make_float2(sv.x * scale, sv.y * scale);
            if (r == ROUTINGS - 1) {
                *(float2*)&out[(size_t)n * 256 + tid * 2] = vv;
            } else {
                *(float2*)&v_s[o * VSTR + g * 2] = vv;
            }
        }
        if (r == ROUTINGS - 1) break;
        __syncthreads();
        // No third barrier: the fused F+A+B touches only registers and
        // read-only pose_s/act_s; its v_s reads (in E) happen right after this
        // barrier, and the next v_s write (next D) is behind the post-C barrier.
    }
}

extern "C" void kernel_launch(void* const* d_in, const int* in_sizes, int n_in,
                              void* d_out, int out_size)
{
    const float* x = (const float*)d_in[0];
    const float* W = (const float*)d_in[1];
    if (n_in >= 2 && in_sizes[0] == 2048) {   // defensive: W has 2048 elems
        const float* t = x; x = W; W = t;
    }
    float* out = (float*)d_out;
    capsule_kernel<<<2 * HO * WO, NTH>>>(x, W, out);
}